// round 2
// baseline (speedup 1.0000x reference)
#include <cuda_runtime.h>
#include <cuda_bf16.h>
#include <math.h>

#define N_NODES 100000
#define N_FEAT  512
#define HIDDEN  128
#define N_CLASS 16
#define N_EDGES 3200000
#define ALPHA   0.25f

// ---------------- scratch (static device globals; no allocation) -------------
__device__ float g_local[(size_t)N_NODES * N_CLASS];   // local_logits
__device__ float g_buf[(size_t)N_NODES * N_CLASS];     // ping buffer for iter 1
__device__ int   g_deg[N_NODES];
__device__ int   g_rowptr[N_NODES + 1];
__device__ int   g_wptr[N_NODES];
__device__ float g_scale[N_NODES];
__device__ int   g_csr[N_EDGES];

// ---------------- CSR build --------------------------------------------------
__global__ void zero_deg_kernel() {
    for (int i = blockIdx.x * blockDim.x + threadIdx.x; i < N_NODES;
         i += gridDim.x * blockDim.x)
        g_deg[i] = 0;
}

__global__ void count_deg_kernel(const int* __restrict__ src) {
    for (int e = blockIdx.x * blockDim.x + threadIdx.x; e < N_EDGES;
         e += gridDim.x * blockDim.x)
        atomicAdd(&g_deg[src[e]], 1);
}

// single block, 1024 threads: exclusive scan of deg -> rowptr, wptr, scale
__global__ void scan_kernel() {
    __shared__ int part[1024];
    const int t  = threadIdx.x;
    const int CH = (N_NODES + 1023) / 1024;
    const int b  = t * CH;
    const int e  = min(b + CH, N_NODES);
    int s = 0;
    for (int i = b; i < e; i++) s += g_deg[i];
    part[t] = s;
    __syncthreads();
    if (t == 0) {
        int run = 0;
        for (int i = 0; i < 1024; i++) { int tmp = part[i]; part[i] = run; run += tmp; }
        g_rowptr[N_NODES] = run;
    }
    __syncthreads();
    int off = part[t];
    for (int i = b; i < e; i++) {
        int d = g_deg[i];
        g_rowptr[i] = off;
        g_wptr[i]   = off;
        g_scale[i]  = (1.0f - ALPHA) / fmaxf((float)d, 1e-12f);
        off += d;
    }
}

__global__ void scatter_kernel(const int* __restrict__ src, const int* __restrict__ dst) {
    for (int e = blockIdx.x * blockDim.x + threadIdx.x; e < N_EDGES;
         e += gridDim.x * blockDim.x) {
        int s = src[e];
        int p = atomicAdd(&g_wptr[s], 1);
        g_csr[p] = dst[e];
    }
}

// ---------------- fused GEMM: local_logits = relu(X @ W1) @ W2 ---------------
// Block: 128 rows x 128 hidden (full H), K-loop over 512 in chunks of 32.
// 256 threads, 8x8 register tile each. Epilogue: relu -> smem -> @W2 -> g_local.
#define SMEM_FLOATS (128 * 132 + 128 * 16)

__global__ __launch_bounds__(256)
void gemm_fused_kernel(const float* __restrict__ X,
                       const float* __restrict__ W1,
                       const float* __restrict__ W2) {
    extern __shared__ float sm[];
    float* Xs = sm;             // [32][128] (k-major)
    float* Ws = sm + 32 * 128;  // [32][128]

    const int tid = threadIdx.x;
    const int r0  = blockIdx.x * 128;
    const int ty  = tid >> 4;   // 0..15
    const int tx  = tid & 15;   // 0..15

    float acc[8][8];
#pragma unroll
    for (int i = 0; i < 8; i++)
#pragma unroll
        for (int j = 0; j < 8; j++) acc[i][j] = 0.0f;

    for (int k0 = 0; k0 < N_FEAT; k0 += 32) {
        // load X tile (128 rows x 32 k), transpose into Xs[k][m]
#pragma unroll
        for (int l = 0; l < 4; l++) {
            int idx = tid + 256 * l;      // 0..1023
            int row = idx >> 3;
            int kv  = idx & 7;
            float4 v = make_float4(0.f, 0.f, 0.f, 0.f);
            int gr = r0 + row;
            if (gr < N_NODES)
                v = *(const float4*)&X[(size_t)gr * N_FEAT + k0 + kv * 4];
            Xs[(kv * 4 + 0) * 128 + row] = v.x;
            Xs[(kv * 4 + 1) * 128 + row] = v.y;
            Xs[(kv * 4 + 2) * 128 + row] = v.z;
            Xs[(kv * 4 + 3) * 128 + row] = v.w;
        }
        // load W1 tile (32 k x 128 n)
#pragma unroll
        for (int l = 0; l < 4; l++) {
            int idx = tid + 256 * l;
            int kr  = idx >> 5;
            int nv  = idx & 31;
            *(float4*)&Ws[kr * 128 + nv * 4] =
                *(const float4*)&W1[(size_t)(k0 + kr) * HIDDEN + nv * 4];
        }
        __syncthreads();
#pragma unroll
        for (int kk = 0; kk < 32; kk++) {
            float a[8], b[8];
            *(float4*)&a[0] = *(float4*)&Xs[kk * 128 + ty * 8];
            *(float4*)&a[4] = *(float4*)&Xs[kk * 128 + ty * 8 + 4];
            *(float4*)&b[0] = *(float4*)&Ws[kk * 128 + tx * 8];
            *(float4*)&b[4] = *(float4*)&Ws[kk * 128 + tx * 8 + 4];
#pragma unroll
            for (int i = 0; i < 8; i++)
#pragma unroll
                for (int j = 0; j < 8; j++)
                    acc[i][j] = fmaf(a[i], b[j], acc[i][j]);
        }
        __syncthreads();
    }

    // epilogue: relu -> Hs, then Hs @ W2
    float* Hs  = sm;                 // [128][132]
    float* W2s = sm + 128 * 132;     // [128][16]
#pragma unroll
    for (int l = 0; l < 2; l++) {
        int idx = tid + 256 * l;     // 0..511 float4s
        *(float4*)&W2s[idx * 4] = *(const float4*)&W2[idx * 4];
    }
#pragma unroll
    for (int i = 0; i < 8; i++) {
#pragma unroll
        for (int j = 0; j < 8; j++)
            Hs[(ty * 8 + i) * 132 + tx * 8 + j] = fmaxf(acc[i][j], 0.0f);
    }
    __syncthreads();

    const int r    = tid >> 1;       // 0..127
    const int half = tid & 1;        // 0..1 -> 8 classes each
    float o[8];
#pragma unroll
    for (int j = 0; j < 8; j++) o[j] = 0.0f;
#pragma unroll 16
    for (int h = 0; h < HIDDEN; h++) {
        float hv  = Hs[r * 132 + h];
        float4 wa = *(float4*)&W2s[h * N_CLASS + half * 8];
        float4 wb = *(float4*)&W2s[h * N_CLASS + half * 8 + 4];
        o[0] = fmaf(hv, wa.x, o[0]); o[1] = fmaf(hv, wa.y, o[1]);
        o[2] = fmaf(hv, wa.z, o[2]); o[3] = fmaf(hv, wa.w, o[3]);
        o[4] = fmaf(hv, wb.x, o[4]); o[5] = fmaf(hv, wb.y, o[5]);
        o[6] = fmaf(hv, wb.z, o[6]); o[7] = fmaf(hv, wb.w, o[7]);
    }
    int gr = r0 + r;
    if (gr < N_NODES) {
        *(float4*)&g_local[(size_t)gr * N_CLASS + half * 8]     = make_float4(o[0], o[1], o[2], o[3]);
        *(float4*)&g_local[(size_t)gr * N_CLASS + half * 8 + 4] = make_float4(o[4], o[5], o[6], o[7]);
    }
}

// ---------------- propagation: 16 threads per node ---------------------------
// PHASE 0: Lin = g_local, out = g_buf (no softmax)
// PHASE 1: Lin = g_buf,   out = d_out (with log_softmax)
template <int PHASE>
__global__ __launch_bounds__(256)
void prop_kernel(float* __restrict__ dout) {
    const int gt = blockIdx.x * blockDim.x + threadIdx.x;
    const int g  = gt >> 4;          // node
    const int c  = gt & 15;          // class
    if (g >= N_NODES) return;

    const float* __restrict__ Lin = (PHASE == 0) ? g_local : g_buf;

    const int beg = g_rowptr[g];
    const int end = g_rowptr[g + 1];
    float acc = 0.0f;
    for (int e = beg; e < end; e++) {
        int d = g_csr[e];
        acc += Lin[(size_t)d * N_CLASS + c];
    }
    float v = g_scale[g] * acc + ALPHA * g_local[(size_t)g * N_CLASS + c];

    if (PHASE == 1) {
        float m = v;
#pragma unroll
        for (int s = 8; s; s >>= 1) m = fmaxf(m, __shfl_xor_sync(0xffffffffu, m, s));
        float ex  = expf(v - m);
        float sum = ex;
#pragma unroll
        for (int s = 8; s; s >>= 1) sum += __shfl_xor_sync(0xffffffffu, sum, s);
        v = (v - m) - logf(sum);
        dout[(size_t)g * N_CLASS + c] = v;
    } else {
        g_buf[(size_t)g * N_CLASS + c] = v;
    }
}

// ---------------- launch -----------------------------------------------------
extern "C" void kernel_launch(void* const* d_in, const int* in_sizes, int n_in,
                              void* d_out, int out_size) {
    const float* x   = (const float*)d_in[0];
    const float* W1  = (const float*)d_in[1];
    const float* W2  = (const float*)d_in[2];
    const int*   esr = (const int*)d_in[3];
    const int*   eds = (const int*)d_in[4];
    float*       out = (float*)d_out;

    cudaFuncSetAttribute(gemm_fused_kernel,
                         cudaFuncAttributeMaxDynamicSharedMemorySize,
                         SMEM_FLOATS * (int)sizeof(float));

    zero_deg_kernel<<<256, 256>>>();
    count_deg_kernel<<<2048, 256>>>(esr);
    scan_kernel<<<1, 1024>>>();
    scatter_kernel<<<2048, 256>>>(esr, eds);

    gemm_fused_kernel<<<(N_NODES + 127) / 128, 256,
                        SMEM_FLOATS * (int)sizeof(float)>>>(x, W1, W2);

    const int PROP_BLOCKS = (N_NODES * 16 + 255) / 256;
    prop_kernel<0><<<PROP_BLOCKS, 256>>>(nullptr);
    prop_kernel<1><<<PROP_BLOCKS, 256>>>(out);
}

// round 4
// speedup vs baseline: 1.4403x; 1.4403x over previous
#include <cuda_runtime.h>
#include <cuda_bf16.h>
#include <math.h>
#include <stdint.h>

#define N_NODES 100000
#define N_FEAT  512
#define HIDDEN  128
#define N_CLASS 16
#define N_EDGES 3200000
#define ALPHA   0.25f

// ---------------- scratch (static device globals; no allocation) -------------
__device__ float g_local[(size_t)N_NODES * N_CLASS];
__device__ float g_buf[(size_t)N_NODES * N_CLASS];
__device__ int   g_deg[N_NODES];
__device__ int   g_rowptr[N_NODES + 1];
__device__ int   g_wptr[N_NODES];
__device__ float g_scale[N_NODES];
__device__ int   g_csr[N_EDGES];

// ---------------- PTX helpers ------------------------------------------------
__device__ __forceinline__ uint32_t smem_u32(const void* p) {
    uint32_t a;
    asm("{ .reg .u64 t; cvta.to.shared.u64 t, %1; cvt.u32.u64 %0, t; }" : "=r"(a) : "l"(p));
    return a;
}
__device__ __forceinline__ void cp_async16(uint32_t dst, const void* src, uint32_t srcsize) {
    asm volatile("cp.async.cg.shared.global [%0], [%1], 16, %2;"
                 :: "r"(dst), "l"(src), "r"(srcsize) : "memory");
}
__device__ __forceinline__ void cp_commit() {
    asm volatile("cp.async.commit_group;" ::: "memory");
}
template <int N>
__device__ __forceinline__ void cp_wait() {
    asm volatile("cp.async.wait_group %0;" :: "n"(N) : "memory");
}
__device__ __forceinline__ uint32_t f2tf32(float x) {
    uint32_t r;
    asm("cvt.rna.tf32.f32 %0, %1;" : "=r"(r) : "f"(x));
    return r;
}
__device__ __forceinline__ void mma_tf32(float* d, const uint32_t* a, const uint32_t* b) {
    asm volatile(
        "mma.sync.aligned.m16n8k8.row.col.f32.tf32.tf32.f32 "
        "{%0,%1,%2,%3}, {%4,%5,%6,%7}, {%8,%9}, {%0,%1,%2,%3};"
        : "+f"(d[0]), "+f"(d[1]), "+f"(d[2]), "+f"(d[3])
        : "r"(a[0]), "r"(a[1]), "r"(a[2]), "r"(a[3]), "r"(b[0]), "r"(b[1]));
}

// ---------------- CSR build --------------------------------------------------
__global__ void zero_deg_kernel() {
    for (int i = blockIdx.x * blockDim.x + threadIdx.x; i < N_NODES;
         i += gridDim.x * blockDim.x)
        g_deg[i] = 0;
}

__global__ void count_deg_kernel(const int* __restrict__ src) {
    for (int e = blockIdx.x * blockDim.x + threadIdx.x; e < N_EDGES;
         e += gridDim.x * blockDim.x)
        atomicAdd(&g_deg[src[e]], 1);
}

// single block, 1024 threads: exclusive scan via shfl
__global__ void scan_kernel() {
    __shared__ int warpsum[32];
    const int t    = threadIdx.x;
    const int lane = t & 31;
    const int w    = t >> 5;
    const int CH   = (N_NODES + 1023) / 1024;
    const int b    = t * CH;
    const int e    = min(b + CH, N_NODES);
    int s = 0;
    for (int i = b; i < e; i++) s += g_deg[i];

    int incl = s;
#pragma unroll
    for (int off = 1; off < 32; off <<= 1) {
        int v = __shfl_up_sync(0xffffffffu, incl, off);
        if (lane >= off) incl += v;
    }
    if (lane == 31) warpsum[w] = incl;
    __syncthreads();
    if (w == 0) {
        int v = warpsum[lane];
        int iv = v;
#pragma unroll
        for (int off = 1; off < 32; off <<= 1) {
            int u = __shfl_up_sync(0xffffffffu, iv, off);
            if (lane >= off) iv += u;
        }
        warpsum[lane] = iv - v;
    }
    __syncthreads();
    int off = warpsum[w] + (incl - s);
    for (int i = b; i < e; i++) {
        int d = g_deg[i];
        g_rowptr[i] = off;
        g_wptr[i]   = off;
        g_scale[i]  = (1.0f - ALPHA) / fmaxf((float)d, 1e-12f);
        off += d;
    }
    if (t == 1023) g_rowptr[N_NODES] = off;
}

__global__ void scatter_kernel(const int* __restrict__ src, const int* __restrict__ dst) {
    for (int e = blockIdx.x * blockDim.x + threadIdx.x; e < N_EDGES;
         e += gridDim.x * blockDim.x) {
        int s = src[e];
        int p = atomicAdd(&g_wptr[s], 1);
        g_csr[p] = dst[e];
    }
}

// ---------------- tf32 mma.sync GEMM: g_local = relu(X@W1) @ W2 --------------
// CTA = 128 rows x 128 (full HIDDEN), 256 threads = 8 warps (2m x 4n),
// warp tile 64x32, mma m16n8k8 tf32. K in chunks of 32, double-buffered cp.async.
// SMEM (floats):
//   A buf b: A_F(b) = b*128*36            (stride 36, padded)
//   B buf b: B_F(b) = 9216 + b*32*132     (stride 132, padded; B[k][n] layout)
//   W2s:     17664 (2048 floats)
//   Hs (epilogue, overlaps A/B): 0, stride 132, 128*132 = 16896 floats
#define A_F(b)   ((b) * 128 * 36)
#define B_F(b)   (9216 + (b) * 32 * 132)
#define W2S_F    17664
#define GEMM_SMEM_FLOATS (17664 + 2048)

__global__ __launch_bounds__(256)
void gemm_mma_kernel(const float* __restrict__ X,
                     const float* __restrict__ W1,
                     const float* __restrict__ W2) {
    extern __shared__ float smf[];
    const uint32_t smb = smem_u32(smf);

    const int tid  = threadIdx.x;
    const int lane = tid & 31;
    const int wid  = tid >> 5;
    const int wm   = wid & 1;        // 0..1  -> m offset wm*64
    const int wn   = wid >> 1;       // 0..3  -> n offset wn*32
    const int r0   = blockIdx.x * 128;

    // W2 -> smem
    {
        *(float4*)&smf[W2S_F + tid * 8]     = *(const float4*)&W2[tid * 8];
        *(float4*)&smf[W2S_F + tid * 8 + 4] = *(const float4*)&W2[tid * 8 + 4];
    }

    // tile-load lambdas (256 threads x 4 float4 each per tile)
    const int a_row = tid >> 3;        // 0..31 (+32*l)
    const int a_kg  = tid & 7;         // 16B group in k (0..7 -> k = kg*4)
    const int b_k   = tid >> 5;        // 0..7 (+8*l)
    const int b_nv  = tid & 31;        // float4 in n

    auto load_chunk = [&](int chunk, int buf) {
        const int k0 = chunk * 32;
#pragma unroll
        for (int l = 0; l < 4; l++) {
            int row  = a_row + l * 32;
            int grow = r0 + row;
            uint32_t sz = (grow < N_NODES) ? 16u : 0u;
            const float* src = X + (size_t)min(grow, N_NODES - 1) * N_FEAT + k0 + a_kg * 4;
            cp_async16(smb + 4 * (A_F(buf) + row * 36 + a_kg * 4), src, sz);
        }
#pragma unroll
        for (int l = 0; l < 4; l++) {
            int k = b_k + l * 8;
            cp_async16(smb + 4 * (B_F(buf) + k * 132 + b_nv * 4),
                       &W1[(size_t)(k0 + k) * HIDDEN + b_nv * 4], 16u);
        }
        cp_commit();
    };

    float acc[4][4][4];
#pragma unroll
    for (int mi = 0; mi < 4; mi++)
#pragma unroll
        for (int ni = 0; ni < 4; ni++)
#pragma unroll
            for (int c = 0; c < 4; c++) acc[mi][ni][c] = 0.0f;

    load_chunk(0, 0);

    const int NCHUNK = N_FEAT / 32;    // 16
#pragma unroll 1
    for (int chunk = 0; chunk < NCHUNK; chunk++) {
        const int buf = chunk & 1;
        if (chunk + 1 < NCHUNK) {
            load_chunk(chunk + 1, buf ^ 1);
            cp_wait<1>();
        } else {
            cp_wait<0>();
        }
        __syncthreads();

        const float* As = &smf[A_F(buf)];
        const float* Bs = &smf[B_F(buf)];
#pragma unroll
        for (int ks = 0; ks < 4; ks++) {
            const int kb = ks * 8;
            uint32_t a[4][4];
#pragma unroll
            for (int mi = 0; mi < 4; mi++) {
                int r = wm * 64 + mi * 16 + (lane >> 2);
                int c = kb + (lane & 3);
                a[mi][0] = f2tf32(As[r * 36 + c]);
                a[mi][1] = f2tf32(As[(r + 8) * 36 + c]);
                a[mi][2] = f2tf32(As[r * 36 + c + 4]);
                a[mi][3] = f2tf32(As[(r + 8) * 36 + c + 4]);
            }
            uint32_t b[4][2];
#pragma unroll
            for (int ni = 0; ni < 4; ni++) {
                int n = wn * 32 + ni * 8 + (lane >> 2);
                int k = kb + (lane & 3);
                b[ni][0] = f2tf32(Bs[k * 132 + n]);
                b[ni][1] = f2tf32(Bs[(k + 4) * 132 + n]);
            }
#pragma unroll
            for (int mi = 0; mi < 4; mi++)
#pragma unroll
                for (int ni = 0; ni < 4; ni++)
                    mma_tf32(acc[mi][ni], a[mi], b[ni]);
        }
        __syncthreads();
    }

    // epilogue: relu -> Hs (overlaps A/B smem), then Hs @ W2 -> g_local
    float* Hs = smf;   // [128][132]
#pragma unroll
    for (int mi = 0; mi < 4; mi++) {
        int rA = wm * 64 + mi * 16 + (lane >> 2);
#pragma unroll
        for (int ni = 0; ni < 4; ni++) {
            int c0 = wn * 32 + ni * 8 + 2 * (lane & 3);
            Hs[rA * 132 + c0]           = fmaxf(acc[mi][ni][0], 0.0f);
            Hs[rA * 132 + c0 + 1]       = fmaxf(acc[mi][ni][1], 0.0f);
            Hs[(rA + 8) * 132 + c0]     = fmaxf(acc[mi][ni][2], 0.0f);
            Hs[(rA + 8) * 132 + c0 + 1] = fmaxf(acc[mi][ni][3], 0.0f);
        }
    }
    __syncthreads();

    const int r    = tid >> 1;
    const int half = tid & 1;
    const float* W2s = &smf[W2S_F];
    float o[8];
#pragma unroll
    for (int j = 0; j < 8; j++) o[j] = 0.0f;
#pragma unroll 16
    for (int h = 0; h < HIDDEN; h++) {
        float hv  = Hs[r * 132 + h];
        float4 wa = *(const float4*)&W2s[h * N_CLASS + half * 8];
        float4 wb = *(const float4*)&W2s[h * N_CLASS + half * 8 + 4];
        o[0] = fmaf(hv, wa.x, o[0]); o[1] = fmaf(hv, wa.y, o[1]);
        o[2] = fmaf(hv, wa.z, o[2]); o[3] = fmaf(hv, wa.w, o[3]);
        o[4] = fmaf(hv, wb.x, o[4]); o[5] = fmaf(hv, wb.y, o[5]);
        o[6] = fmaf(hv, wb.z, o[6]); o[7] = fmaf(hv, wb.w, o[7]);
    }
    int gr = r0 + r;
    if (gr < N_NODES) {
        *(float4*)&g_local[(size_t)gr * N_CLASS + half * 8]     = make_float4(o[0], o[1], o[2], o[3]);
        *(float4*)&g_local[(size_t)gr * N_CLASS + half * 8 + 4] = make_float4(o[4], o[5], o[6], o[7]);
    }
}

// ---------------- propagation: 16 threads per node ---------------------------
template <int PHASE>
__global__ __launch_bounds__(256)
void prop_kernel(float* __restrict__ dout) {
    const int gt = blockIdx.x * blockDim.x + threadIdx.x;
    const int g  = gt >> 4;
    const int c  = gt & 15;
    if (g >= N_NODES) return;

    const float* __restrict__ Lin = (PHASE == 0) ? g_local : g_buf;

    const int beg = g_rowptr[g];
    const int end = g_rowptr[g + 1];
    float acc = 0.0f;
    for (int e = beg; e < end; e++) {
        int d = g_csr[e];
        acc += Lin[(size_t)d * N_CLASS + c];
    }
    float v = g_scale[g] * acc + ALPHA * g_local[(size_t)g * N_CLASS + c];

    if (PHASE == 1) {
        float m = v;
#pragma unroll
        for (int s = 8; s; s >>= 1) m = fmaxf(m, __shfl_xor_sync(0xffffffffu, m, s));
        float ex  = expf(v - m);
        float sum = ex;
#pragma unroll
        for (int s = 8; s; s >>= 1) sum += __shfl_xor_sync(0xffffffffu, sum, s);
        v = (v - m) - logf(sum);
        dout[(size_t)g * N_CLASS + c] = v;
    } else {
        g_buf[(size_t)g * N_CLASS + c] = v;
    }
}

// ---------------- launch -----------------------------------------------------
extern "C" void kernel_launch(void* const* d_in, const int* in_sizes, int n_in,
                              void* d_out, int out_size) {
    const float* x   = (const float*)d_in[0];
    const float* W1  = (const float*)d_in[1];
    const float* W2  = (const float*)d_in[2];
    const int*   esr = (const int*)d_in[3];
    const int*   eds = (const int*)d_in[4];
    float*       out = (float*)d_out;

    cudaFuncSetAttribute(gemm_mma_kernel,
                         cudaFuncAttributeMaxDynamicSharedMemorySize,
                         GEMM_SMEM_FLOATS * (int)sizeof(float));

    // fork CSR build onto a side stream, overlap with GEMM
    // (kernel_launch runs only twice — correctness + capture — so the tiny
    //  stream/event leak is bounded and capture-legal)
    cudaStream_t s2;
    cudaStreamCreateWithFlags(&s2, cudaStreamNonBlocking);
    cudaEvent_t evFork, evJoin;
    cudaEventCreateWithFlags(&evFork, cudaEventDisableTiming);
    cudaEventCreateWithFlags(&evJoin, cudaEventDisableTiming);

    cudaEventRecord(evFork, 0);
    cudaStreamWaitEvent(s2, evFork, 0);

    zero_deg_kernel<<<256, 256, 0, s2>>>();
    count_deg_kernel<<<2048, 256, 0, s2>>>(esr);
    scan_kernel<<<1, 1024, 0, s2>>>();
    scatter_kernel<<<2048, 256, 0, s2>>>(esr, eds);
    cudaEventRecord(evJoin, s2);

    gemm_mma_kernel<<<(N_NODES + 127) / 128, 256,
                      GEMM_SMEM_FLOATS * (int)sizeof(float)>>>(x, W1, W2);

    cudaStreamWaitEvent(0, evJoin, 0);

    const int PROP_BLOCKS = (N_NODES * 16 + 255) / 256;
    prop_kernel<0><<<PROP_BLOCKS, 256>>>(nullptr);
    prop_kernel<1><<<PROP_BLOCKS, 256>>>(out);
}

// round 5
// speedup vs baseline: 1.5224x; 1.0570x over previous
#include <cuda_runtime.h>
#include <cuda_bf16.h>
#include <math.h>
#include <stdint.h>

#define N_NODES 100000
#define N_FEAT  512
#define HIDDEN  128
#define N_CLASS 16
#define N_EDGES 3200000
#define ALPHA   0.25f

// ---------------- scratch (static device globals; no allocation) -------------
__device__ float g_local[(size_t)N_NODES * N_CLASS];
__device__ float g_buf[(size_t)N_NODES * N_CLASS];
__device__ int   g_deg[N_NODES];
__device__ int   g_rowptr[N_NODES + 1];
__device__ int   g_wptr[N_NODES];
__device__ float g_scale[N_NODES];
__device__ int   g_csr[N_EDGES];
__device__ __nv_bfloat16 g_w1bt[(size_t)HIDDEN * N_FEAT];  // W1^T as bf16 [n][k]

// ---------------- PTX helpers ------------------------------------------------
__device__ __forceinline__ uint32_t smem_u32(const void* p) {
    uint32_t a;
    asm("{ .reg .u64 t; cvta.to.shared.u64 t, %1; cvt.u32.u64 %0, t; }" : "=r"(a) : "l"(p));
    return a;
}
__device__ __forceinline__ void cp_async16(uint32_t dst, const void* src, uint32_t srcsize) {
    asm volatile("cp.async.cg.shared.global [%0], [%1], 16, %2;"
                 :: "r"(dst), "l"(src), "r"(srcsize) : "memory");
}
__device__ __forceinline__ void cp_commit() {
    asm volatile("cp.async.commit_group;" ::: "memory");
}
template <int N>
__device__ __forceinline__ void cp_wait() {
    asm volatile("cp.async.wait_group %0;" :: "n"(N) : "memory");
}
// packed bf16x2 from two floats: lo = first element (even k), hi = second
__device__ __forceinline__ uint32_t pack_bf16(float lo, float hi) {
    uint32_t r;
    asm("cvt.rn.bf16x2.f32 %0, %1, %2;" : "=r"(r) : "f"(hi), "f"(lo));
    return r;
}
__device__ __forceinline__ void mma_bf16(float* d, const uint32_t* a, const uint32_t* b) {
    asm volatile(
        "mma.sync.aligned.m16n8k16.row.col.f32.bf16.bf16.f32 "
        "{%0,%1,%2,%3}, {%4,%5,%6,%7}, {%8,%9}, {%0,%1,%2,%3};"
        : "+f"(d[0]), "+f"(d[1]), "+f"(d[2]), "+f"(d[3])
        : "r"(a[0]), "r"(a[1]), "r"(a[2]), "r"(a[3]), "r"(b[0]), "r"(b[1]));
}

// ---------------- CSR build --------------------------------------------------
__global__ void zero_deg_kernel() {
    for (int i = blockIdx.x * blockDim.x + threadIdx.x; i < N_NODES;
         i += gridDim.x * blockDim.x)
        g_deg[i] = 0;
}

__global__ void count_deg_kernel(const int* __restrict__ src) {
    for (int e = blockIdx.x * blockDim.x + threadIdx.x; e < N_EDGES;
         e += gridDim.x * blockDim.x)
        atomicAdd(&g_deg[src[e]], 1);
}

// single block, 1024 threads: exclusive scan via shfl
__global__ void scan_kernel() {
    __shared__ int warpsum[32];
    const int t    = threadIdx.x;
    const int lane = t & 31;
    const int w    = t >> 5;
    const int CH   = (N_NODES + 1023) / 1024;
    const int b    = t * CH;
    const int e    = min(b + CH, N_NODES);
    int s = 0;
    for (int i = b; i < e; i++) s += g_deg[i];

    int incl = s;
#pragma unroll
    for (int off = 1; off < 32; off <<= 1) {
        int v = __shfl_up_sync(0xffffffffu, incl, off);
        if (lane >= off) incl += v;
    }
    if (lane == 31) warpsum[w] = incl;
    __syncthreads();
    if (w == 0) {
        int v = warpsum[lane];
        int iv = v;
#pragma unroll
        for (int off = 1; off < 32; off <<= 1) {
            int u = __shfl_up_sync(0xffffffffu, iv, off);
            if (lane >= off) iv += u;
        }
        warpsum[lane] = iv - v;
    }
    __syncthreads();
    int off = warpsum[w] + (incl - s);
    for (int i = b; i < e; i++) {
        int d = g_deg[i];
        g_rowptr[i] = off;
        g_wptr[i]   = off;
        g_scale[i]  = (1.0f - ALPHA) / fmaxf((float)d, 1e-12f);
        off += d;
    }
    if (t == 1023) g_rowptr[N_NODES] = off;
}

__global__ void scatter_kernel(const int* __restrict__ src, const int* __restrict__ dst) {
    for (int e = blockIdx.x * blockDim.x + threadIdx.x; e < N_EDGES;
         e += gridDim.x * blockDim.x) {
        int s = src[e];
        int p = atomicAdd(&g_wptr[s], 1);
        g_csr[p] = dst[e];
    }
}

// ---------------- W1 -> bf16 transpose: g_w1bt[n][k] = bf16(W1[k][n]) --------
__global__ void conv_w1_kernel(const float* __restrict__ W1) {
    __shared__ float tile[32][33];
    const int bx = blockIdx.x;   // n tile (0..3)
    const int by = blockIdx.y;   // k tile (0..15)
    const int x = threadIdx.x, y = threadIdx.y;   // 32 x 8
#pragma unroll
    for (int i = 0; i < 32; i += 8)
        tile[y + i][x] = W1[(size_t)(by * 32 + y + i) * HIDDEN + bx * 32 + x];
    __syncthreads();
#pragma unroll
    for (int i = 0; i < 32; i += 8)
        g_w1bt[(size_t)(bx * 32 + y + i) * N_FEAT + by * 32 + x] =
            __float2bfloat16(tile[x][y + i]);
}

// ---------------- bf16 mma GEMM: g_local = relu(X@W1) @ W2 -------------------
// CTA = 128 rows x 128 (full HIDDEN), 256 threads = 8 warps (2m x 4n),
// warp tile 64x32, mma m16n8k16 bf16. K chunks of 32, double-buffered cp.async.
// SMEM (float units):
//   A buf b (f32):  A_F(b) = b*128*40  (stride 40 f32; conflict-free LDS.64)
//   B buf b (bf16): base float off 10240, per-buf 2560 f; stride 40 bf16
//   Hs epilogue: [0, 16896) stride 132
//   W2s: 16896 (2048 floats)
#define A_F(b)   ((b) * 128 * 40)
#define B_BASE_F 10240
#define W2S_F    16896
#define GEMM_SMEM_FLOATS (16896 + 2048)

__global__ __launch_bounds__(256)
void gemm_mma_kernel(const float* __restrict__ X, const float* __restrict__ W2) {
    extern __shared__ float smf[];
    const uint32_t smb = smem_u32(smf);
    __nv_bfloat16* smB = (__nv_bfloat16*)(smf + B_BASE_F);   // bf16 units

    const int tid  = threadIdx.x;
    const int lane = tid & 31;
    const int wid  = tid >> 5;
    const int wm   = wid & 1;        // m offset wm*64
    const int wn   = wid >> 1;       // n offset wn*32
    const int r0   = blockIdx.x * 128;

    // W2 -> smem
    *(float4*)&smf[W2S_F + tid * 8]     = *(const float4*)&W2[tid * 8];
    *(float4*)&smf[W2S_F + tid * 8 + 4] = *(const float4*)&W2[tid * 8 + 4];

    // A: 128 rows x 8 chunks of 16B ; B: 128 n x 4 chunks of 16B (8 bf16)
    const int a_row = tid >> 3;      // + 32*l
    const int a_kg  = tid & 7;
    const int b_n   = tid >> 2;      // + 64*l
    const int b_j   = tid & 3;

    auto load_chunk = [&](int chunk, int buf) {
        const int k0 = chunk * 32;
#pragma unroll
        for (int l = 0; l < 4; l++) {
            int row  = a_row + l * 32;
            int grow = r0 + row;
            uint32_t sz = (grow < N_NODES) ? 16u : 0u;
            const float* src = X + (size_t)min(grow, N_NODES - 1) * N_FEAT + k0 + a_kg * 4;
            cp_async16(smb + 4 * (A_F(buf) + row * 40 + a_kg * 4), src, sz);
        }
#pragma unroll
        for (int l = 0; l < 2; l++) {
            int n = b_n + l * 64;
            cp_async16(smb + 4 * B_BASE_F + buf * 10240 + n * 80 + b_j * 16,
                       &g_w1bt[(size_t)n * N_FEAT + k0 + b_j * 8], 16u);
        }
        cp_commit();
    };

    float acc[4][4][4];
#pragma unroll
    for (int mi = 0; mi < 4; mi++)
#pragma unroll
        for (int ni = 0; ni < 4; ni++)
#pragma unroll
            for (int c = 0; c < 4; c++) acc[mi][ni][c] = 0.0f;

    load_chunk(0, 0);

    const int NCHUNK = N_FEAT / 32;    // 16
#pragma unroll 1
    for (int chunk = 0; chunk < NCHUNK; chunk++) {
        const int buf = chunk & 1;
        if (chunk + 1 < NCHUNK) {
            load_chunk(chunk + 1, buf ^ 1);
            cp_wait<1>();
        } else {
            cp_wait<0>();
        }
        __syncthreads();

        const float* As = &smf[A_F(buf)];
        const __nv_bfloat16* Bs = smB + buf * 5120;
#pragma unroll
        for (int ks = 0; ks < 2; ks++) {
            const int kb = ks * 16;
            uint32_t a[4][4];
#pragma unroll
            for (int mi = 0; mi < 4; mi++) {
                int r = wm * 64 + mi * 16 + (lane >> 2);
                int c = kb + 2 * (lane & 3);
                float2 p0 = *(const float2*)&As[r * 40 + c];
                float2 p1 = *(const float2*)&As[(r + 8) * 40 + c];
                float2 p2 = *(const float2*)&As[r * 40 + c + 8];
                float2 p3 = *(const float2*)&As[(r + 8) * 40 + c + 8];
                a[mi][0] = pack_bf16(p0.x, p0.y);
                a[mi][1] = pack_bf16(p1.x, p1.y);
                a[mi][2] = pack_bf16(p2.x, p2.y);
                a[mi][3] = pack_bf16(p3.x, p3.y);
            }
            uint32_t b[4][2];
#pragma unroll
            for (int ni = 0; ni < 4; ni++) {
                int n = wn * 32 + ni * 8 + (lane >> 2);
                int k = kb + 2 * (lane & 3);
                b[ni][0] = *(const uint32_t*)&Bs[n * 40 + k];
                b[ni][1] = *(const uint32_t*)&Bs[n * 40 + k + 8];
            }
#pragma unroll
            for (int mi = 0; mi < 4; mi++)
#pragma unroll
                for (int ni = 0; ni < 4; ni++)
                    mma_bf16(acc[mi][ni], a[mi], b[ni]);
        }
        __syncthreads();
    }

    // epilogue: relu -> Hs (overlaps A/B smem), then Hs @ W2 -> g_local
    float* Hs = smf;   // [128][132]
#pragma unroll
    for (int mi = 0; mi < 4; mi++) {
        int rA = wm * 64 + mi * 16 + (lane >> 2);
#pragma unroll
        for (int ni = 0; ni < 4; ni++) {
            int c0 = wn * 32 + ni * 8 + 2 * (lane & 3);
            Hs[rA * 132 + c0]           = fmaxf(acc[mi][ni][0], 0.0f);
            Hs[rA * 132 + c0 + 1]       = fmaxf(acc[mi][ni][1], 0.0f);
            Hs[(rA + 8) * 132 + c0]     = fmaxf(acc[mi][ni][2], 0.0f);
            Hs[(rA + 8) * 132 + c0 + 1] = fmaxf(acc[mi][ni][3], 0.0f);
        }
    }
    __syncthreads();

    const int r    = tid >> 1;
    const int half = tid & 1;
    const float* W2s = &smf[W2S_F];
    float o[8];
#pragma unroll
    for (int j = 0; j < 8; j++) o[j] = 0.0f;
#pragma unroll 16
    for (int h = 0; h < HIDDEN; h++) {
        float hv  = Hs[r * 132 + h];
        float4 wa = *(const float4*)&W2s[h * N_CLASS + half * 8];
        float4 wb = *(const float4*)&W2s[h * N_CLASS + half * 8 + 4];
        o[0] = fmaf(hv, wa.x, o[0]); o[1] = fmaf(hv, wa.y, o[1]);
        o[2] = fmaf(hv, wa.z, o[2]); o[3] = fmaf(hv, wa.w, o[3]);
        o[4] = fmaf(hv, wb.x, o[4]); o[5] = fmaf(hv, wb.y, o[5]);
        o[6] = fmaf(hv, wb.z, o[6]); o[7] = fmaf(hv, wb.w, o[7]);
    }
    int gr = r0 + r;
    if (gr < N_NODES) {
        *(float4*)&g_local[(size_t)gr * N_CLASS + half * 8]     = make_float4(o[0], o[1], o[2], o[3]);
        *(float4*)&g_local[(size_t)gr * N_CLASS + half * 8 + 4] = make_float4(o[4], o[5], o[6], o[7]);
    }
}

// ---------------- propagation: 4 threads per node, float4 gathers ------------
template <int PHASE>
__global__ __launch_bounds__(256)
void prop_kernel(float* __restrict__ dout) {
    const int gt = blockIdx.x * blockDim.x + threadIdx.x;
    const int g  = gt >> 2;
    const int q  = gt & 3;           // quarter: classes 4q..4q+3
    if (g >= N_NODES) return;

    const float4* __restrict__ Lin =
        (PHASE == 0) ? (const float4*)g_local : (const float4*)g_buf;

    const int beg = g_rowptr[g];
    const int end = g_rowptr[g + 1];
    float4 acc = make_float4(0.f, 0.f, 0.f, 0.f);
#pragma unroll 4
    for (int e = beg; e < end; e++) {
        int d = __ldg(&g_csr[e]);
        float4 t = Lin[(size_t)d * 4 + q];
        acc.x += t.x; acc.y += t.y; acc.z += t.z; acc.w += t.w;
    }
    const float s = g_scale[g];
    float4 loc = ((const float4*)g_local)[(size_t)g * 4 + q];
    float4 v;
    v.x = s * acc.x + ALPHA * loc.x;
    v.y = s * acc.y + ALPHA * loc.y;
    v.z = s * acc.z + ALPHA * loc.z;
    v.w = s * acc.w + ALPHA * loc.w;

    if (PHASE == 1) {
        float m = fmaxf(fmaxf(v.x, v.y), fmaxf(v.z, v.w));
        m = fmaxf(m, __shfl_xor_sync(0xffffffffu, m, 1));
        m = fmaxf(m, __shfl_xor_sync(0xffffffffu, m, 2));
        float sum = expf(v.x - m) + expf(v.y - m) + expf(v.z - m) + expf(v.w - m);
        sum += __shfl_xor_sync(0xffffffffu, sum, 1);
        sum += __shfl_xor_sync(0xffffffffu, sum, 2);
        float ls = m + logf(sum);
        v.x -= ls; v.y -= ls; v.z -= ls; v.w -= ls;
        ((float4*)dout)[(size_t)g * 4 + q] = v;
    } else {
        ((float4*)g_buf)[(size_t)g * 4 + q] = v;
    }
}

// ---------------- launch -----------------------------------------------------
extern "C" void kernel_launch(void* const* d_in, const int* in_sizes, int n_in,
                              void* d_out, int out_size) {
    const float* x   = (const float*)d_in[0];
    const float* W1  = (const float*)d_in[1];
    const float* W2  = (const float*)d_in[2];
    const int*   esr = (const int*)d_in[3];
    const int*   eds = (const int*)d_in[4];
    float*       out = (float*)d_out;

    cudaFuncSetAttribute(gemm_mma_kernel,
                         cudaFuncAttributeMaxDynamicSharedMemorySize,
                         GEMM_SMEM_FLOATS * (int)sizeof(float));

    // fork CSR build onto a side stream, overlap with W1-convert + GEMM
    cudaStream_t s2;
    cudaStreamCreateWithFlags(&s2, cudaStreamNonBlocking);
    cudaEvent_t evFork, evJoin;
    cudaEventCreateWithFlags(&evFork, cudaEventDisableTiming);
    cudaEventCreateWithFlags(&evJoin, cudaEventDisableTiming);

    cudaEventRecord(evFork, 0);
    cudaStreamWaitEvent(s2, evFork, 0);

    zero_deg_kernel<<<256, 256, 0, s2>>>();
    count_deg_kernel<<<2048, 256, 0, s2>>>(esr);
    scan_kernel<<<1, 1024, 0, s2>>>();
    scatter_kernel<<<2048, 256, 0, s2>>>(esr, eds);
    cudaEventRecord(evJoin, s2);

    conv_w1_kernel<<<dim3(4, 16), dim3(32, 8)>>>(W1);
    gemm_mma_kernel<<<(N_NODES + 127) / 128, 256,
                      GEMM_SMEM_FLOATS * (int)sizeof(float)>>>(x, W2);

    cudaStreamWaitEvent(0, evJoin, 0);

    const int PROP_BLOCKS = (N_NODES * 4 + 255) / 256;
    prop_kernel<0><<<PROP_BLOCKS, 256>>>(nullptr);
    prop_kernel<1><<<PROP_BLOCKS, 256>>>(out);
}

// round 6
// speedup vs baseline: 1.7806x; 1.1696x over previous
#include <cuda_runtime.h>
#include <cuda_bf16.h>
#include <math.h>
#include <stdint.h>

#define N_NODES 100000
#define N_FEAT  512
#define HIDDEN  128
#define N_CLASS 16
#define N_EDGES 3200000
#define ALPHA   0.25f

// ---------------- scratch (static device globals; no allocation) -------------
__device__ float g_local[(size_t)N_NODES * N_CLASS];
__device__ float g_buf[(size_t)N_NODES * N_CLASS];
__device__ int   g_deg[N_NODES];
__device__ int   g_rowptr[N_NODES + 1];
__device__ int   g_wptr[N_NODES];
__device__ float g_scale[N_NODES];
__device__ int   g_csr[N_EDGES];
__device__ __nv_bfloat16 g_w1bt[(size_t)HIDDEN * N_FEAT];        // W1^T bf16 [n][k]
__device__ __nv_bfloat16 g_xb[(size_t)N_NODES * N_FEAT];         // X bf16 [node][k]

// ---------------- PTX helpers ------------------------------------------------
__device__ __forceinline__ uint32_t smem_u32(const void* p) {
    uint32_t a;
    asm("{ .reg .u64 t; cvta.to.shared.u64 t, %1; cvt.u32.u64 %0, t; }" : "=r"(a) : "l"(p));
    return a;
}
__device__ __forceinline__ void cp_async16(uint32_t dst, const void* src, uint32_t srcsize) {
    asm volatile("cp.async.cg.shared.global [%0], [%1], 16, %2;"
                 :: "r"(dst), "l"(src), "r"(srcsize) : "memory");
}
__device__ __forceinline__ void cp_commit() {
    asm volatile("cp.async.commit_group;" ::: "memory");
}
template <int N>
__device__ __forceinline__ void cp_wait() {
    asm volatile("cp.async.wait_group %0;" :: "n"(N) : "memory");
}
__device__ __forceinline__ void ldsm_x4(uint32_t* r, uint32_t addr) {
    asm volatile("ldmatrix.sync.aligned.m8n8.x4.shared.b16 {%0,%1,%2,%3}, [%4];"
                 : "=r"(r[0]), "=r"(r[1]), "=r"(r[2]), "=r"(r[3]) : "r"(addr));
}
__device__ __forceinline__ void mma_bf16(float* d, const uint32_t* a, const uint32_t* b) {
    asm volatile(
        "mma.sync.aligned.m16n8k16.row.col.f32.bf16.bf16.f32 "
        "{%0,%1,%2,%3}, {%4,%5,%6,%7}, {%8,%9}, {%0,%1,%2,%3};"
        : "+f"(d[0]), "+f"(d[1]), "+f"(d[2]), "+f"(d[3])
        : "r"(a[0]), "r"(a[1]), "r"(a[2]), "r"(a[3]), "r"(b[0]), "r"(b[1]));
}

// ---------------- CSR build --------------------------------------------------
__global__ void zero_deg_kernel() {
    for (int i = blockIdx.x * blockDim.x + threadIdx.x; i < N_NODES;
         i += gridDim.x * blockDim.x)
        g_deg[i] = 0;
}

__global__ void count_deg_kernel(const int* __restrict__ src) {
    for (int e = blockIdx.x * blockDim.x + threadIdx.x; e < N_EDGES;
         e += gridDim.x * blockDim.x)
        atomicAdd(&g_deg[src[e]], 1);
}

__global__ void scan_kernel() {
    __shared__ int warpsum[32];
    const int t    = threadIdx.x;
    const int lane = t & 31;
    const int w    = t >> 5;
    const int CH   = (N_NODES + 1023) / 1024;
    const int b    = t * CH;
    const int e    = min(b + CH, N_NODES);
    int s = 0;
    for (int i = b; i < e; i++) s += g_deg[i];

    int incl = s;
#pragma unroll
    for (int off = 1; off < 32; off <<= 1) {
        int v = __shfl_up_sync(0xffffffffu, incl, off);
        if (lane >= off) incl += v;
    }
    if (lane == 31) warpsum[w] = incl;
    __syncthreads();
    if (w == 0) {
        int v = warpsum[lane];
        int iv = v;
#pragma unroll
        for (int off = 1; off < 32; off <<= 1) {
            int u = __shfl_up_sync(0xffffffffu, iv, off);
            if (lane >= off) iv += u;
        }
        warpsum[lane] = iv - v;
    }
    __syncthreads();
    int off = warpsum[w] + (incl - s);
    for (int i = b; i < e; i++) {
        int d = g_deg[i];
        g_rowptr[i] = off;
        g_wptr[i]   = off;
        g_scale[i]  = (1.0f - ALPHA) / fmaxf((float)d, 1e-12f);
        off += d;
    }
    if (t == 1023) g_rowptr[N_NODES] = off;
}

__global__ void scatter_kernel(const int* __restrict__ src, const int* __restrict__ dst) {
    for (int e = blockIdx.x * blockDim.x + threadIdx.x; e < N_EDGES;
         e += gridDim.x * blockDim.x) {
        int s = src[e];
        int p = atomicAdd(&g_wptr[s], 1);
        g_csr[p] = dst[e];
    }
}

// ---------------- X -> bf16 --------------------------------------------------
__global__ __launch_bounds__(256)
void conv_x_kernel(const float* __restrict__ X) {
    const size_t total4 = (size_t)N_NODES * N_FEAT / 4;
    for (size_t i = blockIdx.x * blockDim.x + threadIdx.x; i < total4;
         i += (size_t)gridDim.x * blockDim.x) {
        float4 v = *(const float4*)&X[i * 4];
        uint32_t p0, p1;
        asm("cvt.rn.bf16x2.f32 %0, %1, %2;" : "=r"(p0) : "f"(v.y), "f"(v.x));
        asm("cvt.rn.bf16x2.f32 %0, %1, %2;" : "=r"(p1) : "f"(v.w), "f"(v.z));
        *(uint2*)&g_xb[i * 4] = make_uint2(p0, p1);
    }
}

// ---------------- W1 -> bf16 transpose: g_w1bt[n][k] -------------------------
__global__ void conv_w1_kernel(const float* __restrict__ W1) {
    __shared__ float tile[32][33];
    const int bx = blockIdx.x;   // n tile (0..3)
    const int by = blockIdx.y;   // k tile (0..15)
    const int x = threadIdx.x, y = threadIdx.y;   // 32 x 8
#pragma unroll
    for (int i = 0; i < 32; i += 8)
        tile[y + i][x] = W1[(size_t)(by * 32 + y + i) * HIDDEN + bx * 32 + x];
    __syncthreads();
#pragma unroll
    for (int i = 0; i < 32; i += 8)
        g_w1bt[(size_t)(bx * 32 + y + i) * N_FEAT + by * 32 + x] =
            __float2bfloat16(tile[x][y + i]);
}

// ---------------- bf16 ldmatrix GEMM: g_local = relu(X@W1) @ W2 --------------
// CTA = 128 rows x 128 (full HIDDEN), 256 threads = 8 warps (2m x 4n),
// warp tile 64x32, mma m16n8k16 bf16. K chunks of 64, double-buffered cp.async.
// SMEM (bytes): A buf b at b*18432 (128 rows x 144B, stride 72 bf16)
//               B buf b at 36864 + b*18432 (128 n x 144B)
//               W2s at 73728 (8 KB)
//               Hs epilogue overlays [0, 67584) as float stride 132
#define AB_STRIDE_B 144
#define A_BYTE(b)   ((b) * 18432)
#define B_BYTE(b)   (36864 + (b) * 18432)
#define W2S_BYTE    73728
#define GEMM_SMEM_BYTES (73728 + 8192)

__global__ __launch_bounds__(256)
void gemm_mma_kernel(const float* __restrict__ W2) {
    extern __shared__ char smc[];
    float* smf = (float*)smc;
    const uint32_t smb = smem_u32(smc);

    const int tid  = threadIdx.x;
    const int lane = tid & 31;
    const int wid  = tid >> 5;
    const int wm   = wid & 1;        // m offset wm*64
    const int wn   = wid >> 1;       // n offset wn*32
    const int r0   = blockIdx.x * 128;

    // W2 -> smem
    float* W2s = (float*)(smc + W2S_BYTE);
    *(float4*)&W2s[tid * 8]     = *(const float4*)&W2[tid * 8];
    *(float4*)&W2s[tid * 8 + 4] = *(const float4*)&W2[tid * 8 + 4];

    // tile loads: 128 rows x 128B per operand; 256 thr x 4 cp.async16 each
    const int t_row = tid >> 3;      // +32*l
    const int t_g   = tid & 7;       // 16B group (8 bf16)

    auto load_chunk = [&](int chunk, int buf) {
        const int k0 = chunk * 64;
#pragma unroll
        for (int l = 0; l < 4; l++) {
            int row  = t_row + l * 32;
            int grow = r0 + row;
            uint32_t sz = (grow < N_NODES) ? 16u : 0u;
            cp_async16(smb + A_BYTE(buf) + row * AB_STRIDE_B + t_g * 16,
                       &g_xb[(size_t)min(grow, N_NODES - 1) * N_FEAT + k0 + t_g * 8], sz);
        }
#pragma unroll
        for (int l = 0; l < 4; l++) {
            int n = t_row + l * 32;
            cp_async16(smb + B_BYTE(buf) + n * AB_STRIDE_B + t_g * 16,
                       &g_w1bt[(size_t)n * N_FEAT + k0 + t_g * 8], 16u);
        }
        cp_commit();
    };

    float acc[4][4][4];
#pragma unroll
    for (int mi = 0; mi < 4; mi++)
#pragma unroll
        for (int ni = 0; ni < 4; ni++)
#pragma unroll
            for (int c = 0; c < 4; c++) acc[mi][ni][c] = 0.0f;

    // per-lane ldmatrix source rows/cols
    const int a_row  = wm * 64 + (lane & 7) + ((lane >> 3) & 1) * 8;
    const int a_koff = (lane >> 4) * 8;
    const int b_n    = wn * 32 + (lane & 7) + ((lane >> 4) & 1) * 8;
    const int b_koff = ((lane >> 3) & 1) * 8;

    load_chunk(0, 0);

    const int NCHUNK = N_FEAT / 64;    // 8
#pragma unroll 1
    for (int chunk = 0; chunk < NCHUNK; chunk++) {
        const int buf = chunk & 1;
        if (chunk + 1 < NCHUNK) {
            load_chunk(chunk + 1, buf ^ 1);
            cp_wait<1>();
        } else {
            cp_wait<0>();
        }
        __syncthreads();

        const uint32_t Abase = smb + A_BYTE(buf);
        const uint32_t Bbase = smb + B_BYTE(buf);
#pragma unroll
        for (int ks = 0; ks < 4; ks++) {
            const int kb = ks * 16;
            uint32_t a[4][4];
#pragma unroll
            for (int mi = 0; mi < 4; mi++)
                ldsm_x4(a[mi], Abase + (a_row + mi * 16) * AB_STRIDE_B
                                     + (kb + a_koff) * 2);
            uint32_t b[4][2];
#pragma unroll
            for (int np = 0; np < 2; np++) {
                uint32_t r[4];
                ldsm_x4(r, Bbase + (b_n + np * 16) * AB_STRIDE_B
                                 + (kb + b_koff) * 2);
                b[np * 2][0]     = r[0];
                b[np * 2][1]     = r[1];
                b[np * 2 + 1][0] = r[2];
                b[np * 2 + 1][1] = r[3];
            }
#pragma unroll
            for (int mi = 0; mi < 4; mi++)
#pragma unroll
                for (int ni = 0; ni < 4; ni++)
                    mma_bf16(acc[mi][ni], a[mi], b[ni]);
        }
        __syncthreads();
    }

    // epilogue: relu -> Hs (overlays A/B smem), then Hs @ W2 -> g_local
    float* Hs = smf;   // [128][132]
#pragma unroll
    for (int mi = 0; mi < 4; mi++) {
        int rA = wm * 64 + mi * 16 + (lane >> 2);
#pragma unroll
        for (int ni = 0; ni < 4; ni++) {
            int c0 = wn * 32 + ni * 8 + 2 * (lane & 3);
            Hs[rA * 132 + c0]           = fmaxf(acc[mi][ni][0], 0.0f);
            Hs[rA * 132 + c0 + 1]       = fmaxf(acc[mi][ni][1], 0.0f);
            Hs[(rA + 8) * 132 + c0]     = fmaxf(acc[mi][ni][2], 0.0f);
            Hs[(rA + 8) * 132 + c0 + 1] = fmaxf(acc[mi][ni][3], 0.0f);
        }
    }
    __syncthreads();

    const int r    = tid >> 1;
    const int half = tid & 1;
    float o[8];
#pragma unroll
    for (int j = 0; j < 8; j++) o[j] = 0.0f;
#pragma unroll 16
    for (int h = 0; h < HIDDEN; h++) {
        float hv  = Hs[r * 132 + h];
        float4 wa = *(const float4*)&W2s[h * N_CLASS + half * 8];
        float4 wb = *(const float4*)&W2s[h * N_CLASS + half * 8 + 4];
        o[0] = fmaf(hv, wa.x, o[0]); o[1] = fmaf(hv, wa.y, o[1]);
        o[2] = fmaf(hv, wa.z, o[2]); o[3] = fmaf(hv, wa.w, o[3]);
        o[4] = fmaf(hv, wb.x, o[4]); o[5] = fmaf(hv, wb.y, o[5]);
        o[6] = fmaf(hv, wb.z, o[6]); o[7] = fmaf(hv, wb.w, o[7]);
    }
    int gr = r0 + r;
    if (gr < N_NODES) {
        *(float4*)&g_local[(size_t)gr * N_CLASS + half * 8]     = make_float4(o[0], o[1], o[2], o[3]);
        *(float4*)&g_local[(size_t)gr * N_CLASS + half * 8 + 4] = make_float4(o[4], o[5], o[6], o[7]);
    }
}

// ---------------- propagation: 4 threads per node, 8-wide MLP strips ---------
template <int PHASE>
__global__ __launch_bounds__(256)
void prop_kernel(float* __restrict__ dout) {
    const int gt = blockIdx.x * blockDim.x + threadIdx.x;
    const int g  = gt >> 2;
    const int q  = gt & 3;           // classes 4q..4q+3
    if (g >= N_NODES) return;

    const float4* __restrict__ Lin =
        (PHASE == 0) ? (const float4*)g_local : (const float4*)g_buf;

    const int beg = g_rowptr[g];
    const int end = g_rowptr[g + 1];
    float4 acc = make_float4(0.f, 0.f, 0.f, 0.f);

    int e = beg;
#pragma unroll 1
    for (; e + 8 <= end; e += 8) {
        int d[8];
#pragma unroll
        for (int j = 0; j < 8; j++) d[j] = __ldg(&g_csr[e + j]);
        float4 t[8];
#pragma unroll
        for (int j = 0; j < 8; j++) t[j] = Lin[(size_t)d[j] * 4 + q];
#pragma unroll
        for (int j = 0; j < 8; j++) {
            acc.x += t[j].x; acc.y += t[j].y; acc.z += t[j].z; acc.w += t[j].w;
        }
    }
    for (; e < end; e++) {
        int d = __ldg(&g_csr[e]);
        float4 t = Lin[(size_t)d * 4 + q];
        acc.x += t.x; acc.y += t.y; acc.z += t.z; acc.w += t.w;
    }

    const float s = g_scale[g];
    float4 loc = ((const float4*)g_local)[(size_t)g * 4 + q];
    float4 v;
    v.x = s * acc.x + ALPHA * loc.x;
    v.y = s * acc.y + ALPHA * loc.y;
    v.z = s * acc.z + ALPHA * loc.z;
    v.w = s * acc.w + ALPHA * loc.w;

    if (PHASE == 1) {
        float m = fmaxf(fmaxf(v.x, v.y), fmaxf(v.z, v.w));
        m = fmaxf(m, __shfl_xor_sync(0xffffffffu, m, 1));
        m = fmaxf(m, __shfl_xor_sync(0xffffffffu, m, 2));
        float sum = expf(v.x - m) + expf(v.y - m) + expf(v.z - m) + expf(v.w - m);
        sum += __shfl_xor_sync(0xffffffffu, sum, 1);
        sum += __shfl_xor_sync(0xffffffffu, sum, 2);
        float ls = m + logf(sum);
        v.x -= ls; v.y -= ls; v.z -= ls; v.w -= ls;
        ((float4*)dout)[(size_t)g * 4 + q] = v;
    } else {
        ((float4*)g_buf)[(size_t)g * 4 + q] = v;
    }
}

// ---------------- launch -----------------------------------------------------
extern "C" void kernel_launch(void* const* d_in, const int* in_sizes, int n_in,
                              void* d_out, int out_size) {
    const float* x   = (const float*)d_in[0];
    const float* W1  = (const float*)d_in[1];
    const float* W2  = (const float*)d_in[2];
    const int*   esr = (const int*)d_in[3];
    const int*   eds = (const int*)d_in[4];
    float*       out = (float*)d_out;

    cudaFuncSetAttribute(gemm_mma_kernel,
                         cudaFuncAttributeMaxDynamicSharedMemorySize,
                         GEMM_SMEM_BYTES);

    // fork CSR build onto a side stream, overlap with X/W1 convert + GEMM
    cudaStream_t s2;
    cudaStreamCreateWithFlags(&s2, cudaStreamNonBlocking);
    cudaEvent_t evFork, evJoin;
    cudaEventCreateWithFlags(&evFork, cudaEventDisableTiming);
    cudaEventCreateWithFlags(&evJoin, cudaEventDisableTiming);

    cudaEventRecord(evFork, 0);
    cudaStreamWaitEvent(s2, evFork, 0);

    zero_deg_kernel<<<256, 256, 0, s2>>>();
    count_deg_kernel<<<2048, 256, 0, s2>>>(esr);
    scan_kernel<<<1, 1024, 0, s2>>>();
    scatter_kernel<<<2048, 256, 0, s2>>>(esr, eds);
    cudaEventRecord(evJoin, s2);

    conv_x_kernel<<<4096, 256>>>(x);
    conv_w1_kernel<<<dim3(4, 16), dim3(32, 8)>>>(W1);
    gemm_mma_kernel<<<(N_NODES + 127) / 128, 256, GEMM_SMEM_BYTES>>>(W2);

    cudaStreamWaitEvent(0, evJoin, 0);

    const int PROP_BLOCKS = (N_NODES * 4 + 255) / 256;
    prop_kernel<0><<<PROP_BLOCKS, 256>>>(nullptr);
    prop_kernel<1><<<PROP_BLOCKS, 256>>>(out);
}

// round 8
// speedup vs baseline: 1.8118x; 1.0175x over previous
#include <cuda_runtime.h>
#include <cuda_bf16.h>
#include <cuda_fp16.h>
#include <math.h>
#include <stdint.h>

#define N_NODES 100000
#define N_FEAT  512
#define HIDDEN  128
#define N_CLASS 16
#define N_EDGES 3200000
#define ALPHA   0.25f

// ---------------- scratch (static device globals; no allocation) -------------
__device__ float  g_local[(size_t)N_NODES * N_CLASS];          // fp32 local logits
__device__ __half g_loc16[(size_t)N_NODES * N_CLASS];          // fp16 copy (gather)
__device__ __half g_buf16[(size_t)N_NODES * N_CLASS];          // fp16 iter-1 out
__device__ int    g_deg[N_NODES];
__device__ int    g_rowptr[N_NODES + 1];
__device__ int    g_wptr[N_NODES];
__device__ float  g_scale[N_NODES];
__device__ int    g_csr[N_EDGES];
__device__ __nv_bfloat16 g_w1bt[(size_t)HIDDEN * N_FEAT];      // W1^T bf16 [n][k]
__device__ __nv_bfloat16 g_xb[(size_t)N_NODES * N_FEAT];       // X bf16 [node][k]

// ---------------- PTX helpers ------------------------------------------------
__device__ __forceinline__ uint32_t smem_u32(const void* p) {
    uint32_t a;
    asm("{ .reg .u64 t; cvta.to.shared.u64 t, %1; cvt.u32.u64 %0, t; }" : "=r"(a) : "l"(p));
    return a;
}
__device__ __forceinline__ void cp_async16(uint32_t dst, const void* src, uint32_t srcsize) {
    asm volatile("cp.async.cg.shared.global [%0], [%1], 16, %2;"
                 :: "r"(dst), "l"(src), "r"(srcsize) : "memory");
}
__device__ __forceinline__ void cp_commit() {
    asm volatile("cp.async.commit_group;" ::: "memory");
}
template <int N>
__device__ __forceinline__ void cp_wait() {
    asm volatile("cp.async.wait_group %0;" :: "n"(N) : "memory");
}
__device__ __forceinline__ void ldsm_x4(uint32_t* r, uint32_t addr) {
    asm volatile("ldmatrix.sync.aligned.m8n8.x4.shared.b16 {%0,%1,%2,%3}, [%4];"
                 : "=r"(r[0]), "=r"(r[1]), "=r"(r[2]), "=r"(r[3]) : "r"(addr));
}
__device__ __forceinline__ void mma_bf16(float* d, const uint32_t* a, const uint32_t* b) {
    asm volatile(
        "mma.sync.aligned.m16n8k16.row.col.f32.bf16.bf16.f32 "
        "{%0,%1,%2,%3}, {%4,%5,%6,%7}, {%8,%9}, {%0,%1,%2,%3};"
        : "+f"(d[0]), "+f"(d[1]), "+f"(d[2]), "+f"(d[3])
        : "r"(a[0]), "r"(a[1]), "r"(a[2]), "r"(a[3]), "r"(b[0]), "r"(b[1]));
}

// ---------------- CSR build --------------------------------------------------
__global__ void zero_deg_kernel() {
    for (int i = blockIdx.x * blockDim.x + threadIdx.x; i < N_NODES;
         i += gridDim.x * blockDim.x)
        g_deg[i] = 0;
}

__global__ void count_deg_kernel(const int* __restrict__ src) {
    for (int e = blockIdx.x * blockDim.x + threadIdx.x; e < N_EDGES;
         e += gridDim.x * blockDim.x)
        atomicAdd(&g_deg[src[e]], 1);
}

__global__ void scan_kernel() {
    __shared__ int warpsum[32];
    const int t    = threadIdx.x;
    const int lane = t & 31;
    const int w    = t >> 5;
    const int CH   = (N_NODES + 1023) / 1024;
    const int b    = t * CH;
    const int e    = min(b + CH, N_NODES);
    int s = 0;
    for (int i = b; i < e; i++) s += g_deg[i];

    int incl = s;
#pragma unroll
    for (int off = 1; off < 32; off <<= 1) {
        int v = __shfl_up_sync(0xffffffffu, incl, off);
        if (lane >= off) incl += v;
    }
    if (lane == 31) warpsum[w] = incl;
    __syncthreads();
    if (w == 0) {
        int v = warpsum[lane];
        int iv = v;
#pragma unroll
        for (int off = 1; off < 32; off <<= 1) {
            int u = __shfl_up_sync(0xffffffffu, iv, off);
            if (lane >= off) iv += u;
        }
        warpsum[lane] = iv - v;
    }
    __syncthreads();
    int off = warpsum[w] + (incl - s);
    for (int i = b; i < e; i++) {
        int d = g_deg[i];
        g_rowptr[i] = off;
        g_wptr[i]   = off;
        g_scale[i]  = (1.0f - ALPHA) / fmaxf((float)d, 1e-12f);
        off += d;
    }
    if (t == 1023) g_rowptr[N_NODES] = off;
}

__global__ void scatter_kernel(const int* __restrict__ src, const int* __restrict__ dst) {
    for (int e = blockIdx.x * blockDim.x + threadIdx.x; e < N_EDGES;
         e += gridDim.x * blockDim.x) {
        int s = src[e];
        int p = atomicAdd(&g_wptr[s], 1);
        g_csr[p] = dst[e];
    }
}

// ---------------- X -> bf16 --------------------------------------------------
__global__ __launch_bounds__(256)
void conv_x_kernel(const float* __restrict__ X) {
    const size_t total4 = (size_t)N_NODES * N_FEAT / 4;
    for (size_t i = blockIdx.x * blockDim.x + threadIdx.x; i < total4;
         i += (size_t)gridDim.x * blockDim.x) {
        float4 v = *(const float4*)&X[i * 4];
        uint32_t p0, p1;
        asm("cvt.rn.bf16x2.f32 %0, %1, %2;" : "=r"(p0) : "f"(v.y), "f"(v.x));
        asm("cvt.rn.bf16x2.f32 %0, %1, %2;" : "=r"(p1) : "f"(v.w), "f"(v.z));
        *(uint2*)&g_xb[i * 4] = make_uint2(p0, p1);
    }
}

// ---------------- W1 -> bf16 transpose: g_w1bt[n][k] -------------------------
__global__ void conv_w1_kernel(const float* __restrict__ W1) {
    __shared__ float tile[32][33];
    const int bx = blockIdx.x;
    const int by = blockIdx.y;
    const int x = threadIdx.x, y = threadIdx.y;
#pragma unroll
    for (int i = 0; i < 32; i += 8)
        tile[y + i][x] = W1[(size_t)(by * 32 + y + i) * HIDDEN + bx * 32 + x];
    __syncthreads();
#pragma unroll
    for (int i = 0; i < 32; i += 8)
        g_w1bt[(size_t)(bx * 32 + y + i) * N_FEAT + by * 32 + x] =
            __float2bfloat16(tile[x][y + i]);
}

// ---------------- bf16 ldmatrix GEMM (2 CTAs/SM) -----------------------------
// CTA = 128 x 128, 256 threads = 8 warps (2m x 4n), warp tile 64x32.
// K chunks of 32, double buffered. Stride 80B rows (conflict-free ldmatrix).
// SMEM: A bufs [0,20480), B bufs [20480,40960); epilogue Hs fp32 overlays
// [0,67584) stride 132; W2s at 67584 (8KB). Total 75776B -> 2 CTAs/SM.
#define AB_STRIDE 80
#define A_BYTE(b)   ((b) * 10240)
#define B_BYTE(b)   (20480 + (b) * 10240)
#define W2S_BYTE    67584
#define GEMM_SMEM_BYTES (67584 + 8192)

__global__ __launch_bounds__(256, 2)
void gemm_mma_kernel(const float* __restrict__ W2) {
    extern __shared__ char smc[];
    float* smf = (float*)smc;
    const uint32_t smb = smem_u32(smc);

    const int tid  = threadIdx.x;
    const int lane = tid & 31;
    const int wid  = tid >> 5;
    const int wm   = wid & 1;
    const int wn   = wid >> 1;
    const int r0   = blockIdx.x * 128;

    float* W2s = (float*)(smc + W2S_BYTE);
    *(float4*)&W2s[tid * 8]     = *(const float4*)&W2[tid * 8];
    *(float4*)&W2s[tid * 8 + 4] = *(const float4*)&W2[tid * 8 + 4];

    // tile loads: per chunk each operand is 128 rows x 64B = 512 x 16B
    const int t_row = tid >> 2;     // +64*l
    const int t_g   = tid & 3;

    auto load_chunk = [&](int chunk, int buf) {
        const int k0 = chunk * 32;
#pragma unroll
        for (int l = 0; l < 2; l++) {
            int row  = t_row + l * 64;
            int grow = r0 + row;
            uint32_t sz = (grow < N_NODES) ? 16u : 0u;
            cp_async16(smb + A_BYTE(buf) + row * AB_STRIDE + t_g * 16,
                       &g_xb[(size_t)min(grow, N_NODES - 1) * N_FEAT + k0 + t_g * 8], sz);
        }
#pragma unroll
        for (int l = 0; l < 2; l++) {
            int n = t_row + l * 64;
            cp_async16(smb + B_BYTE(buf) + n * AB_STRIDE + t_g * 16,
                       &g_w1bt[(size_t)n * N_FEAT + k0 + t_g * 8], 16u);
        }
        cp_commit();
    };

    float acc[4][4][4];
#pragma unroll
    for (int mi = 0; mi < 4; mi++)
#pragma unroll
        for (int ni = 0; ni < 4; ni++)
#pragma unroll
            for (int c = 0; c < 4; c++) acc[mi][ni][c] = 0.0f;

    const int a_row  = wm * 64 + (lane & 7) + ((lane >> 3) & 1) * 8;
    const int a_koff = (lane >> 4) * 8;
    const int b_n    = wn * 32 + (lane & 7) + ((lane >> 4) & 1) * 8;
    const int b_koff = ((lane >> 3) & 1) * 8;

    load_chunk(0, 0);

    const int NCHUNK = N_FEAT / 32;    // 16
#pragma unroll 1
    for (int chunk = 0; chunk < NCHUNK; chunk++) {
        const int buf = chunk & 1;
        if (chunk + 1 < NCHUNK) {
            load_chunk(chunk + 1, buf ^ 1);
            cp_wait<1>();
        } else {
            cp_wait<0>();
        }
        __syncthreads();

        const uint32_t Abase = smb + A_BYTE(buf);
        const uint32_t Bbase = smb + B_BYTE(buf);
#pragma unroll
        for (int ks = 0; ks < 2; ks++) {
            const int kb = ks * 16;
            uint32_t a[4][4];
#pragma unroll
            for (int mi = 0; mi < 4; mi++)
                ldsm_x4(a[mi], Abase + (a_row + mi * 16) * AB_STRIDE
                                     + (kb + a_koff) * 2);
            uint32_t b[4][2];
#pragma unroll
            for (int np = 0; np < 2; np++) {
                uint32_t r[4];
                ldsm_x4(r, Bbase + (b_n + np * 16) * AB_STRIDE
                                 + (kb + b_koff) * 2);
                b[np * 2][0]     = r[0];
                b[np * 2][1]     = r[1];
                b[np * 2 + 1][0] = r[2];
                b[np * 2 + 1][1] = r[3];
            }
#pragma unroll
            for (int mi = 0; mi < 4; mi++)
#pragma unroll
                for (int ni = 0; ni < 4; ni++)
                    mma_bf16(acc[mi][ni], a[mi], b[ni]);
        }
        __syncthreads();
    }

    // epilogue: relu -> Hs fp32 (overlays mainloop bufs), then @W2
    float* Hs = smf;   // [128][132]
#pragma unroll
    for (int mi = 0; mi < 4; mi++) {
        int rA = wm * 64 + mi * 16 + (lane >> 2);
#pragma unroll
        for (int ni = 0; ni < 4; ni++) {
            int c0 = wn * 32 + ni * 8 + 2 * (lane & 3);
            Hs[rA * 132 + c0]           = fmaxf(acc[mi][ni][0], 0.0f);
            Hs[rA * 132 + c0 + 1]       = fmaxf(acc[mi][ni][1], 0.0f);
            Hs[(rA + 8) * 132 + c0]     = fmaxf(acc[mi][ni][2], 0.0f);
            Hs[(rA + 8) * 132 + c0 + 1] = fmaxf(acc[mi][ni][3], 0.0f);
        }
    }
    __syncthreads();

    const int r    = tid >> 1;
    const int half = tid & 1;
    float o[8];
#pragma unroll
    for (int j = 0; j < 8; j++) o[j] = 0.0f;
#pragma unroll 16
    for (int h = 0; h < HIDDEN; h++) {
        float hv  = Hs[r * 132 + h];
        float4 wa = *(const float4*)&W2s[h * N_CLASS + half * 8];
        float4 wb = *(const float4*)&W2s[h * N_CLASS + half * 8 + 4];
        o[0] = fmaf(hv, wa.x, o[0]); o[1] = fmaf(hv, wa.y, o[1]);
        o[2] = fmaf(hv, wa.z, o[2]); o[3] = fmaf(hv, wa.w, o[3]);
        o[4] = fmaf(hv, wb.x, o[4]); o[5] = fmaf(hv, wb.y, o[5]);
        o[6] = fmaf(hv, wb.z, o[6]); o[7] = fmaf(hv, wb.w, o[7]);
    }
    int gr = r0 + r;
    if (gr < N_NODES) {
        *(float4*)&g_local[(size_t)gr * N_CLASS + half * 8]     = make_float4(o[0], o[1], o[2], o[3]);
        *(float4*)&g_local[(size_t)gr * N_CLASS + half * 8 + 4] = make_float4(o[4], o[5], o[6], o[7]);
        __half2 h01 = __floats2half2_rn(o[0], o[1]);
        __half2 h23 = __floats2half2_rn(o[2], o[3]);
        __half2 h45 = __floats2half2_rn(o[4], o[5]);
        __half2 h67 = __floats2half2_rn(o[6], o[7]);
        uint4 pk = make_uint4(*(uint32_t*)&h01, *(uint32_t*)&h23,
                              *(uint32_t*)&h45, *(uint32_t*)&h67);
        ((uint4*)g_loc16)[(size_t)gr * 2 + half] = pk;
    }
}

// ---------------- propagation: 2 threads/node, fp16 gather, fp32 accum -------
template <int PHASE>
__global__ __launch_bounds__(256)
void prop_kernel(float* __restrict__ dout) {
    const int gt = blockIdx.x * blockDim.x + threadIdx.x;
    const int g  = gt >> 1;
    const int hf = gt & 1;           // classes 8*hf .. 8*hf+7
    if (g >= N_NODES) return;

    const uint4* __restrict__ Lin =
        (PHASE == 0) ? (const uint4*)g_loc16 : (const uint4*)g_buf16;

    const int beg = g_rowptr[g];
    const int end = g_rowptr[g + 1];
    float2 a0 = make_float2(0.f, 0.f), a1 = a0, a2 = a0, a3 = a0;

    int e = beg;
#pragma unroll 1
    for (; e + 8 <= end; e += 8) {
        int d[8];
#pragma unroll
        for (int j = 0; j < 8; j++) d[j] = __ldg(&g_csr[e + j]);
        uint4 t[8];
#pragma unroll
        for (int j = 0; j < 8; j++) t[j] = Lin[(size_t)d[j] * 2 + hf];
#pragma unroll
        for (int j = 0; j < 8; j++) {
            float2 f0 = __half22float2(*(const __half2*)&t[j].x);
            float2 f1 = __half22float2(*(const __half2*)&t[j].y);
            float2 f2 = __half22float2(*(const __half2*)&t[j].z);
            float2 f3 = __half22float2(*(const __half2*)&t[j].w);
            a0.x += f0.x; a0.y += f0.y; a1.x += f1.x; a1.y += f1.y;
            a2.x += f2.x; a2.y += f2.y; a3.x += f3.x; a3.y += f3.y;
        }
    }
    for (; e < end; e++) {
        int d = __ldg(&g_csr[e]);
        uint4 t = Lin[(size_t)d * 2 + hf];
        float2 f0 = __half22float2(*(const __half2*)&t.x);
        float2 f1 = __half22float2(*(const __half2*)&t.y);
        float2 f2 = __half22float2(*(const __half2*)&t.z);
        float2 f3 = __half22float2(*(const __half2*)&t.w);
        a0.x += f0.x; a0.y += f0.y; a1.x += f1.x; a1.y += f1.y;
        a2.x += f2.x; a2.y += f2.y; a3.x += f3.x; a3.y += f3.y;
    }

    const float s = g_scale[g];
    float4 l0 = *(const float4*)&g_local[(size_t)g * N_CLASS + hf * 8];
    float4 l1 = *(const float4*)&g_local[(size_t)g * N_CLASS + hf * 8 + 4];
    float v[8];
    v[0] = s * a0.x + ALPHA * l0.x;  v[1] = s * a0.y + ALPHA * l0.y;
    v[2] = s * a1.x + ALPHA * l0.z;  v[3] = s * a1.y + ALPHA * l0.w;
    v[4] = s * a2.x + ALPHA * l1.x;  v[5] = s * a2.y + ALPHA * l1.y;
    v[6] = s * a3.x + ALPHA * l1.z;  v[7] = s * a3.y + ALPHA * l1.w;

    if (PHASE == 1) {
        float m = v[0];
#pragma unroll
        for (int j = 1; j < 8; j++) m = fmaxf(m, v[j]);
        m = fmaxf(m, __shfl_xor_sync(0xffffffffu, m, 1));
        float sum = 0.0f;
#pragma unroll
        for (int j = 0; j < 8; j++) sum += expf(v[j] - m);
        sum += __shfl_xor_sync(0xffffffffu, sum, 1);
        float ls = m + logf(sum);
        float4 o0 = make_float4(v[0] - ls, v[1] - ls, v[2] - ls, v[3] - ls);
        float4 o1 = make_float4(v[4] - ls, v[5] - ls, v[6] - ls, v[7] - ls);
        *(float4*)&dout[(size_t)g * N_CLASS + hf * 8]     = o0;
        *(float4*)&dout[(size_t)g * N_CLASS + hf * 8 + 4] = o1;
    } else {
        __half2 h01 = __floats2half2_rn(v[0], v[1]);
        __half2 h23 = __floats2half2_rn(v[2], v[3]);
        __half2 h45 = __floats2half2_rn(v[4], v[5]);
        __half2 h67 = __floats2half2_rn(v[6], v[7]);
        uint4 pk = make_uint4(*(uint32_t*)&h01, *(uint32_t*)&h23,
                              *(uint32_t*)&h45, *(uint32_t*)&h67);
        ((uint4*)g_buf16)[(size_t)g * 2 + hf] = pk;
    }
}

// ---------------- launch -----------------------------------------------------
extern "C" void kernel_launch(void* const* d_in, const int* in_sizes, int n_in,
                              void* d_out, int out_size) {
    const float* x   = (const float*)d_in[0];
    const float* W1  = (const float*)d_in[1];
    const float* W2  = (const float*)d_in[2];
    const int*   esr = (const int*)d_in[3];
    const int*   eds = (const int*)d_in[4];
    float*       out = (float*)d_out;

    // lazy one-time stream/event setup (identical resources on every call)
    static cudaStream_t s2 = nullptr;
    static cudaEvent_t evFork = nullptr, evJoin = nullptr;
    static bool smem_set = false;
    if (!s2) {
        cudaStreamCreateWithFlags(&s2, cudaStreamNonBlocking);
        cudaEventCreateWithFlags(&evFork, cudaEventDisableTiming);
        cudaEventCreateWithFlags(&evJoin, cudaEventDisableTiming);
    }
    if (!smem_set) {
        cudaFuncSetAttribute(gemm_mma_kernel,
                             cudaFuncAttributeMaxDynamicSharedMemorySize,
                             GEMM_SMEM_BYTES);
        smem_set = true;
    }

    cudaEventRecord(evFork, 0);
    cudaStreamWaitEvent(s2, evFork, 0);

    zero_deg_kernel<<<256, 256, 0, s2>>>();
    count_deg_kernel<<<2048, 256, 0, s2>>>(esr);
    scan_kernel<<<1, 1024, 0, s2>>>();
    scatter_kernel<<<2048, 256, 0, s2>>>(esr, eds);
    cudaEventRecord(evJoin, s2);

    conv_w1_kernel<<<dim3(4, 16), dim3(32, 8)>>>(W1);
    conv_x_kernel<<<4096, 256>>>(x);
    gemm_mma_kernel<<<(N_NODES + 127) / 128, 256, GEMM_SMEM_BYTES>>>(W2);

    cudaStreamWaitEvent(0, evJoin, 0);

    const int PROP_BLOCKS = (N_NODES * 2 + 255) / 256;
    prop_kernel<0><<<PROP_BLOCKS, 256>>>(nullptr);
    prop_kernel<1><<<PROP_BLOCKS, 256>>>(out);
}